// round 6
// baseline (speedup 1.0000x reference)
#include <cuda_runtime.h>
#include <cstdint>

#define N_NODES 100000
#define N_EDGES 1600000
#define DIM     128

// ---------------- scratch (no allocations allowed) ----------------
__device__ int g_deg[N_NODES];
__device__ int g_rowptr[N_NODES + 1];
__device__ int g_wcur[N_NODES];
__device__ int g_esrc[N_EDGES];
__device__ __align__(16) float g_bufA[(size_t)N_NODES * DIM];
__device__ __align__(16) float g_bufB[(size_t)N_NODES * DIM];

// ---------------- CSR build ----------------
__global__ void zero_deg_kernel() {
    int i = blockIdx.x * blockDim.x + threadIdx.x;
    if (i < N_NODES) g_deg[i] = 0;
}

__global__ void count_kernel(const int* __restrict__ ei) {
    int e = blockIdx.x * blockDim.x + threadIdx.x;
    if (e < N_EDGES) atomicAdd(&g_deg[ei[N_EDGES + e]], 1);
}

__global__ void scan_kernel() {
    __shared__ int s[1024];
    int tid = threadIdx.x;
    const int per = (N_NODES + 1023) / 1024;
    int start = tid * per;
    int end = min(start + per, N_NODES);
    int sum = 0;
    for (int i = start; i < end; i++) sum += g_deg[i];
    s[tid] = sum;
    __syncthreads();
    #pragma unroll
    for (int off = 1; off < 1024; off <<= 1) {
        int v = (tid >= off) ? s[tid - off] : 0;
        __syncthreads();
        s[tid] += v;
        __syncthreads();
    }
    int run = (tid == 0) ? 0 : s[tid - 1];
    for (int i = start; i < end; i++) {
        g_rowptr[i] = run;
        g_wcur[i]   = run;
        run += g_deg[i];
    }
    if (tid == 0) g_rowptr[N_NODES] = s[1023];
}

__global__ void fill_kernel(const int* __restrict__ ei) {
    int e = blockIdx.x * blockDim.x + threadIdx.x;
    if (e < N_EDGES) {
        int d = ei[N_EDGES + e];
        int pos = atomicAdd(&g_wcur[d], 1);
        g_esrc[pos] = ei[e];
    }
}

// ---------------- aggregation: one warp per node, unrolled x8 for MLP ----------------
__global__ void agg_kernel(const float4* __restrict__ x, float4* __restrict__ out) {
    int gw = (blockIdx.x * blockDim.x + threadIdx.x) >> 5;
    if (gw >= N_NODES) return;
    int lane = threadIdx.x & 31;
    float4 acc = x[(size_t)gw * 32 + lane];   // self term (eps=0 GIN)
    float4 ac1 = make_float4(0.f, 0.f, 0.f, 0.f);
    int beg = g_rowptr[gw];
    int end = g_rowptr[gw + 1];
    int e = beg;

    // 8-edge batches: 8 independent index loads, then 8 independent gathers (MLP~8)
    for (; e + 8 <= end; e += 8) {
        int s0 = g_esrc[e+0], s1 = g_esrc[e+1], s2 = g_esrc[e+2], s3 = g_esrc[e+3];
        int s4 = g_esrc[e+4], s5 = g_esrc[e+5], s6 = g_esrc[e+6], s7 = g_esrc[e+7];
        float4 v0 = __ldg(&x[(size_t)s0 * 32 + lane]);
        float4 v1 = __ldg(&x[(size_t)s1 * 32 + lane]);
        float4 v2 = __ldg(&x[(size_t)s2 * 32 + lane]);
        float4 v3 = __ldg(&x[(size_t)s3 * 32 + lane]);
        float4 v4 = __ldg(&x[(size_t)s4 * 32 + lane]);
        float4 v5 = __ldg(&x[(size_t)s5 * 32 + lane]);
        float4 v6 = __ldg(&x[(size_t)s6 * 32 + lane]);
        float4 v7 = __ldg(&x[(size_t)s7 * 32 + lane]);
        acc.x += v0.x + v2.x; acc.y += v0.y + v2.y; acc.z += v0.z + v2.z; acc.w += v0.w + v2.w;
        ac1.x += v1.x + v3.x; ac1.y += v1.y + v3.y; ac1.z += v1.z + v3.z; ac1.w += v1.w + v3.w;
        acc.x += v4.x + v6.x; acc.y += v4.y + v6.y; acc.z += v4.z + v6.z; acc.w += v4.w + v6.w;
        ac1.x += v5.x + v7.x; ac1.y += v5.y + v7.y; ac1.z += v5.z + v7.z; ac1.w += v5.w + v7.w;
    }
    // 2-edge tail batches
    for (; e + 2 <= end; e += 2) {
        int s0 = g_esrc[e+0], s1 = g_esrc[e+1];
        float4 v0 = __ldg(&x[(size_t)s0 * 32 + lane]);
        float4 v1 = __ldg(&x[(size_t)s1 * 32 + lane]);
        acc.x += v0.x; acc.y += v0.y; acc.z += v0.z; acc.w += v0.w;
        ac1.x += v1.x; ac1.y += v1.y; ac1.z += v1.z; ac1.w += v1.w;
    }
    if (e < end) {
        int s0 = g_esrc[e];
        float4 v0 = __ldg(&x[(size_t)s0 * 32 + lane]);
        acc.x += v0.x; acc.y += v0.y; acc.z += v0.z; acc.w += v0.w;
    }
    acc.x += ac1.x; acc.y += ac1.y; acc.z += ac1.z; acc.w += ac1.w;
    out[(size_t)gw * 32 + lane] = acc;
}

// ================= mma.sync tf32 fused MLP (sm_100-legal) =================
#define W_STRIDE 132
#define SM_H   0
#define SM_W1  (128 * W_STRIDE * 4)
#define SM_W2  (2 * 128 * W_STRIDE * 4)
#define SM_B   (3 * 128 * W_STRIDE * 4)
#define MLP_SMEM (SM_B + 1024)

__device__ __forceinline__ uint32_t f2tf32(float f) {
    uint32_t r;
    asm("cvt.rna.tf32.f32 %0, %1;" : "=r"(r) : "f"(f));
    return r;
}

__device__ __forceinline__ void mma16n8k8(float* c,
                                          uint32_t a0, uint32_t a1, uint32_t a2, uint32_t a3,
                                          uint32_t b0, uint32_t b1) {
    asm volatile(
        "mma.sync.aligned.m16n8k8.row.col.f32.tf32.tf32.f32 "
        "{%0,%1,%2,%3}, {%4,%5,%6,%7}, {%8,%9}, {%0,%1,%2,%3};"
        : "+f"(c[0]), "+f"(c[1]), "+f"(c[2]), "+f"(c[3])
        : "r"(a0), "r"(a1), "r"(a2), "r"(a3), "r"(b0), "r"(b1));
}

__global__ void __launch_bounds__(256, 1)
mlp_mma(const float* __restrict__ h,
        const float* __restrict__ W1, const float* __restrict__ b1,
        const float* __restrict__ W2, const float* __restrict__ b2,
        float* __restrict__ out, int relu_out)
{
    extern __shared__ __align__(16) char sm[];
    float*    sH  = (float*)(sm + SM_H);
    uint32_t* sW1 = (uint32_t*)(sm + SM_W1);
    uint32_t* sW2 = (uint32_t*)(sm + SM_W2);
    float*    sB1 = (float*)(sm + SM_B);
    float*    sB2 = sB1 + 128;

    const int tid  = threadIdx.x;
    const int wid  = tid >> 5;
    const int lane = tid & 31;
    const int gid  = lane >> 2;   // 0..7
    const int tig  = lane & 3;    // 0..3

    for (int i = tid; i < 16384; i += 256) {
        int k = i >> 7, n = i & 127;
        sW1[k * W_STRIDE + n] = f2tf32(W1[i]);
        sW2[k * W_STRIDE + n] = f2tf32(W2[i]);
    }
    if (tid < 128) { sB1[tid] = b1[tid]; sB2[tid] = b2[tid]; }
    __syncthreads();

    const int m0 = wid * 16;
    const int ntiles = (N_NODES + 127) / 128;

    for (int t = blockIdx.x; t < ntiles; t += gridDim.x) {
        const int row0 = t * 128;

        __syncwarp();
        #pragma unroll 4
        for (int r = 0; r < 16; r++) {
            int gr = row0 + m0 + r;
            float4 v = (gr < N_NODES) ? *(const float4*)(h + (size_t)gr * DIM + lane * 4)
                                      : make_float4(0.f, 0.f, 0.f, 0.f);
            *(float4*)(sH + (m0 + r) * W_STRIDE + lane * 4) = v;
        }
        __syncwarp();

        float acc[16][4];
        #pragma unroll
        for (int f = 0; f < 16; f++) { acc[f][0] = acc[f][1] = acc[f][2] = acc[f][3] = 0.f; }

        const float* arow = sH + (m0 + gid) * W_STRIDE;
        #pragma unroll 2
        for (int ks = 0; ks < 16; ks++) {
            const int k0 = ks * 8;
            uint32_t a0 = f2tf32(arow[k0 + tig]);
            uint32_t a1 = f2tf32(arow[8 * W_STRIDE + k0 + tig]);
            uint32_t a2 = f2tf32(arow[k0 + tig + 4]);
            uint32_t a3 = f2tf32(arow[8 * W_STRIDE + k0 + tig + 4]);
            const uint32_t* bk0 = sW1 + (k0 + tig) * W_STRIDE + gid;
            const uint32_t* bk1 = bk0 + 4 * W_STRIDE;
            #pragma unroll
            for (int f = 0; f < 16; f++)
                mma16n8k8(acc[f], a0, a1, a2, a3, bk0[f * 8], bk1[f * 8]);
        }

        __syncwarp();
        #pragma unroll
        for (int f = 0; f < 16; f++) {
            int col = 8 * f + 2 * tig;
            float v0 = fmaxf(acc[f][0] + sB1[col],     0.f);
            float v1 = fmaxf(acc[f][1] + sB1[col + 1], 0.f);
            float v2 = fmaxf(acc[f][2] + sB1[col],     0.f);
            float v3 = fmaxf(acc[f][3] + sB1[col + 1], 0.f);
            *(float2*)(sH + (m0 + gid) * W_STRIDE + col)     = make_float2(v0, v1);
            *(float2*)(sH + (m0 + gid + 8) * W_STRIDE + col) = make_float2(v2, v3);
        }
        __syncwarp();

        #pragma unroll
        for (int f = 0; f < 16; f++) { acc[f][0] = acc[f][1] = acc[f][2] = acc[f][3] = 0.f; }

        #pragma unroll 2
        for (int ks = 0; ks < 16; ks++) {
            const int k0 = ks * 8;
            uint32_t a0 = f2tf32(arow[k0 + tig]);
            uint32_t a1 = f2tf32(arow[8 * W_STRIDE + k0 + tig]);
            uint32_t a2 = f2tf32(arow[k0 + tig + 4]);
            uint32_t a3 = f2tf32(arow[8 * W_STRIDE + k0 + tig + 4]);
            const uint32_t* bk0 = sW2 + (k0 + tig) * W_STRIDE + gid;
            const uint32_t* bk1 = bk0 + 4 * W_STRIDE;
            #pragma unroll
            for (int f = 0; f < 16; f++)
                mma16n8k8(acc[f], a0, a1, a2, a3, bk0[f * 8], bk1[f * 8]);
        }

        const int gr0 = row0 + m0 + gid;
        const int gr1 = gr0 + 8;
        #pragma unroll
        for (int f = 0; f < 16; f++) {
            int col = 8 * f + 2 * tig;
            if (gr0 < N_NODES) {
                float v0 = acc[f][0] + sB2[col];
                float v1 = acc[f][1] + sB2[col + 1];
                if (relu_out) { v0 = fmaxf(v0, 0.f); v1 = fmaxf(v1, 0.f); }
                *(float2*)(out + (size_t)gr0 * DIM + col) = make_float2(v0, v1);
            }
            if (gr1 < N_NODES) {
                float v2 = acc[f][2] + sB2[col];
                float v3 = acc[f][3] + sB2[col + 1];
                if (relu_out) { v2 = fmaxf(v2, 0.f); v3 = fmaxf(v3, 0.f); }
                *(float2*)(out + (size_t)gr1 * DIM + col) = make_float2(v2, v3);
            }
        }
    }
}

// ---------------- launch ----------------
extern "C" void kernel_launch(void* const* d_in, const int* in_sizes, int n_in,
                              void* d_out, int out_size)
{
    const float* x  = (const float*)d_in[0];
    const int*   ei = (const int*)d_in[1];
    const float* W1 = (const float*)d_in[2];
    const float* b1 = (const float*)d_in[3];
    const float* W2 = (const float*)d_in[4];
    const float* b2 = (const float*)d_in[5];
    float* out = (float*)d_out;

    static float* bufA = nullptr;
    static float* bufB = nullptr;
    if (!bufA) {
        void *pA, *pB;
        cudaGetSymbolAddress(&pA, g_bufA);
        cudaGetSymbolAddress(&pB, g_bufB);
        bufA = (float*)pA;
        bufB = (float*)pB;
        cudaFuncSetAttribute(mlp_mma, cudaFuncAttributeMaxDynamicSharedMemorySize, MLP_SMEM);
    }

    // CSR build
    zero_deg_kernel<<<(N_NODES + 255) / 256, 256>>>();
    count_kernel<<<(N_EDGES + 255) / 256, 256>>>(ei);
    scan_kernel<<<1, 1024>>>();
    fill_kernel<<<(N_EDGES + 255) / 256, 256>>>(ei);

    const int agg_grid = (N_NODES * 32 + 255) / 256;

    // layer 0
    agg_kernel<<<agg_grid, 256>>>((const float4*)x, (float4*)bufB);
    mlp_mma<<<148, 256, MLP_SMEM>>>(bufB, W1, b1, W2, b2, bufA, 1);
    // layer 1
    agg_kernel<<<agg_grid, 256>>>((const float4*)bufA, (float4*)bufB);
    mlp_mma<<<148, 256, MLP_SMEM>>>(bufB, W1 + 16384, b1 + 128, W2 + 16384, b2 + 128, bufA, 1);
    // layer 2
    agg_kernel<<<agg_grid, 256>>>((const float4*)bufA, (float4*)bufB);
    mlp_mma<<<148, 256, MLP_SMEM>>>(bufB, W1 + 32768, b1 + 256, W2 + 32768, b2 + 256, out, 0);
}

// round 7
// speedup vs baseline: 1.1011x; 1.1011x over previous
#include <cuda_runtime.h>
#include <cstdint>

#define N_NODES 100000
#define N_EDGES 1600000
#define DIM     128

// ---------------- scratch (no allocations allowed) ----------------
__device__ int g_deg[N_NODES];
__device__ int g_rowptr[N_NODES + 1];
__device__ int g_wcur[N_NODES];
__device__ int g_esrc[N_EDGES];
__device__ __align__(16) float g_bufA[(size_t)N_NODES * DIM];
__device__ __align__(16) float g_bufB[(size_t)N_NODES * DIM];

// ---------------- CSR build ----------------
__global__ void zero_deg_kernel() {
    int i = blockIdx.x * blockDim.x + threadIdx.x;
    if (i < N_NODES) g_deg[i] = 0;
}

__global__ void count_kernel(const int* __restrict__ ei) {
    int e = blockIdx.x * blockDim.x + threadIdx.x;
    if (e < N_EDGES) atomicAdd(&g_deg[ei[N_EDGES + e]], 1);
}

__global__ void scan_kernel() {
    __shared__ int s[1024];
    int tid = threadIdx.x;
    const int per = (N_NODES + 1023) / 1024;
    int start = tid * per;
    int end = min(start + per, N_NODES);
    int sum = 0;
    for (int i = start; i < end; i++) sum += g_deg[i];
    s[tid] = sum;
    __syncthreads();
    #pragma unroll
    for (int off = 1; off < 1024; off <<= 1) {
        int v = (tid >= off) ? s[tid - off] : 0;
        __syncthreads();
        s[tid] += v;
        __syncthreads();
    }
    int run = (tid == 0) ? 0 : s[tid - 1];
    for (int i = start; i < end; i++) {
        g_rowptr[i] = run;
        g_wcur[i]   = run;
        run += g_deg[i];
    }
    if (tid == 0) g_rowptr[N_NODES] = s[1023];
}

__global__ void fill_kernel(const int* __restrict__ ei) {
    int e = blockIdx.x * blockDim.x + threadIdx.x;
    if (e < N_EDGES) {
        int d = ei[N_EDGES + e];
        int pos = atomicAdd(&g_wcur[d], 1);
        g_esrc[pos] = ei[e];
    }
}

// ---------------- aggregation: one warp per node (R5 known-good) ----------------
__global__ void agg_kernel(const float4* __restrict__ x, float4* __restrict__ out) {
    int gw = (blockIdx.x * blockDim.x + threadIdx.x) >> 5;
    if (gw >= N_NODES) return;
    int lane = threadIdx.x & 31;
    float4 acc = x[(size_t)gw * 32 + lane];
    int beg = g_rowptr[gw];
    int end = g_rowptr[gw + 1];
    for (int e = beg; e < end; e++) {
        int s = g_esrc[e];
        float4 v = __ldg(&x[(size_t)s * 32 + lane]);
        acc.x += v.x; acc.y += v.y; acc.z += v.z; acc.w += v.w;
    }
    out[(size_t)gw * 32 + lane] = acc;
}

// ================= mma.sync tf32 fused MLP =================
// Warp partition: each of 8 warps = 2 m16-slabs x 8 n8-frags.
// B fragments reused across the 2 slabs -> LDS/warp/kstep: 36 -> 24.
#define W_STRIDE 132
#define SM_H   0
#define SM_W1  (128 * W_STRIDE * 4)
#define SM_W2  (2 * 128 * W_STRIDE * 4)
#define SM_B   (3 * 128 * W_STRIDE * 4)
#define MLP_SMEM (SM_B + 1024)

__device__ __forceinline__ uint32_t f2tf32(float f) {
    uint32_t r;
    asm("cvt.rna.tf32.f32 %0, %1;" : "=r"(r) : "f"(f));
    return r;
}

__device__ __forceinline__ void mma16n8k8(float* c,
                                          uint32_t a0, uint32_t a1, uint32_t a2, uint32_t a3,
                                          uint32_t b0, uint32_t b1) {
    asm volatile(
        "mma.sync.aligned.m16n8k8.row.col.f32.tf32.tf32.f32 "
        "{%0,%1,%2,%3}, {%4,%5,%6,%7}, {%8,%9}, {%0,%1,%2,%3};"
        : "+f"(c[0]), "+f"(c[1]), "+f"(c[2]), "+f"(c[3])
        : "r"(a0), "r"(a1), "r"(a2), "r"(a3), "r"(b0), "r"(b1));
}

__global__ void __launch_bounds__(256, 1)
mlp_mma(const float* __restrict__ h,
        const float* __restrict__ W1, const float* __restrict__ b1,
        const float* __restrict__ W2, const float* __restrict__ b2,
        float* __restrict__ out, int relu_out)
{
    extern __shared__ __align__(16) char sm[];
    float*    sH  = (float*)(sm + SM_H);
    uint32_t* sW1 = (uint32_t*)(sm + SM_W1);
    uint32_t* sW2 = (uint32_t*)(sm + SM_W2);
    float*    sB1 = (float*)(sm + SM_B);
    float*    sB2 = sB1 + 128;

    const int tid  = threadIdx.x;
    const int wid  = tid >> 5;
    const int lane = tid & 31;
    const int gid  = lane >> 2;   // 0..7
    const int tig  = lane & 3;    // 0..3
    const int fh   = wid & 1;     // n half: fh*64
    const int sp   = wid >> 1;    // slab pair: rows sp*32 .. sp*32+31
    const int nbase = fh * 64;
    const int mbase = sp * 32;

    for (int i = tid; i < 16384; i += 256) {
        int k = i >> 7, n = i & 127;
        sW1[k * W_STRIDE + n] = f2tf32(W1[i]);
        sW2[k * W_STRIDE + n] = f2tf32(W2[i]);
    }
    if (tid < 128) { sB1[tid] = b1[tid]; sB2[tid] = b2[tid]; }
    __syncthreads();

    const int ntiles = (N_NODES + 127) / 128;
    const float* arow0 = sH + (mbase + gid) * W_STRIDE;
    const float* arow1 = arow0 + 16 * W_STRIDE;

    for (int t = blockIdx.x; t < ntiles; t += gridDim.x) {
        const int row0 = t * 128;

        // ---- stage tile block-wide (fp32, zero-padded) ----
        for (int i = tid; i < 128 * 32; i += 256) {
            int r = i >> 5, c4 = i & 31;
            int gr = row0 + r;
            float4 v = (gr < N_NODES) ? *(const float4*)(h + (size_t)gr * DIM + c4 * 4)
                                      : make_float4(0.f, 0.f, 0.f, 0.f);
            *(float4*)(sH + r * W_STRIDE + c4 * 4) = v;
        }
        __syncthreads();

        float acc[2][8][4];
        #pragma unroll
        for (int s = 0; s < 2; s++)
            #pragma unroll
            for (int f = 0; f < 8; f++)
                acc[s][f][0] = acc[s][f][1] = acc[s][f][2] = acc[s][f][3] = 0.f;

        // ---- GEMM1 ----
        #pragma unroll 2
        for (int ks = 0; ks < 16; ks++) {
            const int k0 = ks * 8;
            uint32_t a00 = f2tf32(arow0[k0 + tig]);
            uint32_t a01 = f2tf32(arow0[8 * W_STRIDE + k0 + tig]);
            uint32_t a02 = f2tf32(arow0[k0 + tig + 4]);
            uint32_t a03 = f2tf32(arow0[8 * W_STRIDE + k0 + tig + 4]);
            uint32_t a10 = f2tf32(arow1[k0 + tig]);
            uint32_t a11 = f2tf32(arow1[8 * W_STRIDE + k0 + tig]);
            uint32_t a12 = f2tf32(arow1[k0 + tig + 4]);
            uint32_t a13 = f2tf32(arow1[8 * W_STRIDE + k0 + tig + 4]);
            const uint32_t* bk0 = sW1 + (k0 + tig) * W_STRIDE + nbase + gid;
            const uint32_t* bk1 = bk0 + 4 * W_STRIDE;
            #pragma unroll
            for (int f = 0; f < 8; f++) {
                uint32_t b0 = bk0[f * 8], b1 = bk1[f * 8];
                mma16n8k8(acc[0][f], a00, a01, a02, a03, b0, b1);
                mma16n8k8(acc[1][f], a10, a11, a12, a13, b0, b1);
            }
        }

        // ---- epilogue1: relu(acc + b1) -> sH (own 32 rows x own 64 cols) ----
        __syncthreads();   // all warps done reading sH for GEMM1
        #pragma unroll
        for (int s = 0; s < 2; s++) {
            int ra = mbase + s * 16 + gid;
            #pragma unroll
            for (int f = 0; f < 8; f++) {
                int col = nbase + 8 * f + 2 * tig;
                float v0 = fmaxf(acc[s][f][0] + sB1[col],     0.f);
                float v1 = fmaxf(acc[s][f][1] + sB1[col + 1], 0.f);
                float v2 = fmaxf(acc[s][f][2] + sB1[col],     0.f);
                float v3 = fmaxf(acc[s][f][3] + sB1[col + 1], 0.f);
                *(float2*)(sH + ra * W_STRIDE + col)       = make_float2(v0, v1);
                *(float2*)(sH + (ra + 8) * W_STRIDE + col) = make_float2(v2, v3);
            }
        }
        __syncthreads();   // partner warp's columns visible for GEMM2

        #pragma unroll
        for (int s = 0; s < 2; s++)
            #pragma unroll
            for (int f = 0; f < 8; f++)
                acc[s][f][0] = acc[s][f][1] = acc[s][f][2] = acc[s][f][3] = 0.f;

        // ---- GEMM2 ----
        #pragma unroll 2
        for (int ks = 0; ks < 16; ks++) {
            const int k0 = ks * 8;
            uint32_t a00 = f2tf32(arow0[k0 + tig]);
            uint32_t a01 = f2tf32(arow0[8 * W_STRIDE + k0 + tig]);
            uint32_t a02 = f2tf32(arow0[k0 + tig + 4]);
            uint32_t a03 = f2tf32(arow0[8 * W_STRIDE + k0 + tig + 4]);
            uint32_t a10 = f2tf32(arow1[k0 + tig]);
            uint32_t a11 = f2tf32(arow1[8 * W_STRIDE + k0 + tig]);
            uint32_t a12 = f2tf32(arow1[k0 + tig + 4]);
            uint32_t a13 = f2tf32(arow1[8 * W_STRIDE + k0 + tig + 4]);
            const uint32_t* bk0 = sW2 + (k0 + tig) * W_STRIDE + nbase + gid;
            const uint32_t* bk1 = bk0 + 4 * W_STRIDE;
            #pragma unroll
            for (int f = 0; f < 8; f++) {
                uint32_t b0 = bk0[f * 8], b1 = bk1[f * 8];
                mma16n8k8(acc[0][f], a00, a01, a02, a03, b0, b1);
                mma16n8k8(acc[1][f], a10, a11, a12, a13, b0, b1);
            }
        }

        // ---- epilogue2: acc + b2 (+relu) -> gmem ----
        #pragma unroll
        for (int s = 0; s < 2; s++) {
            const int gr0 = row0 + mbase + s * 16 + gid;
            const int gr1 = gr0 + 8;
            #pragma unroll
            for (int f = 0; f < 8; f++) {
                int col = nbase + 8 * f + 2 * tig;
                if (gr0 < N_NODES) {
                    float v0 = acc[s][f][0] + sB2[col];
                    float v1 = acc[s][f][1] + sB2[col + 1];
                    if (relu_out) { v0 = fmaxf(v0, 0.f); v1 = fmaxf(v1, 0.f); }
                    *(float2*)(out + (size_t)gr0 * DIM + col) = make_float2(v0, v1);
                }
                if (gr1 < N_NODES) {
                    float v2 = acc[s][f][2] + sB2[col];
                    float v3 = acc[s][f][3] + sB2[col + 1];
                    if (relu_out) { v2 = fmaxf(v2, 0.f); v3 = fmaxf(v3, 0.f); }
                    *(float2*)(out + (size_t)gr1 * DIM + col) = make_float2(v2, v3);
                }
            }
        }
        __syncthreads();   // protect sH from next-tile staging
    }
}

// ---------------- launch ----------------
extern "C" void kernel_launch(void* const* d_in, const int* in_sizes, int n_in,
                              void* d_out, int out_size)
{
    const float* x  = (const float*)d_in[0];
    const int*   ei = (const int*)d_in[1];
    const float* W1 = (const float*)d_in[2];
    const float* b1 = (const float*)d_in[3];
    const float* W2 = (const float*)d_in[4];
    const float* b2 = (const float*)d_in[5];
    float* out = (float*)d_out;

    static float* bufA = nullptr;
    static float* bufB = nullptr;
    if (!bufA) {
        void *pA, *pB;
        cudaGetSymbolAddress(&pA, g_bufA);
        cudaGetSymbolAddress(&pB, g_bufB);
        bufA = (float*)pA;
        bufB = (float*)pB;
        cudaFuncSetAttribute(mlp_mma, cudaFuncAttributeMaxDynamicSharedMemorySize, MLP_SMEM);
    }

    // CSR build
    zero_deg_kernel<<<(N_NODES + 255) / 256, 256>>>();
    count_kernel<<<(N_EDGES + 255) / 256, 256>>>(ei);
    scan_kernel<<<1, 1024>>>();
    fill_kernel<<<(N_EDGES + 255) / 256, 256>>>(ei);

    const int agg_grid = (N_NODES * 32 + 255) / 256;

    // layer 0
    agg_kernel<<<agg_grid, 256>>>((const float4*)x, (float4*)bufB);
    mlp_mma<<<148, 256, MLP_SMEM>>>(bufB, W1, b1, W2, b2, bufA, 1);
    // layer 1
    agg_kernel<<<agg_grid, 256>>>((const float4*)bufA, (float4*)bufB);
    mlp_mma<<<148, 256, MLP_SMEM>>>(bufB, W1 + 16384, b1 + 128, W2 + 16384, b2 + 128, bufA, 1);
    // layer 2
    agg_kernel<<<agg_grid, 256>>>((const float4*)bufA, (float4*)bufB);
    mlp_mma<<<148, 256, MLP_SMEM>>>(bufB, W1 + 32768, b1 + 256, W2 + 32768, b2 + 256, out, 0);
}